// round 11
// baseline (speedup 1.0000x reference)
#include <cuda_runtime.h>
#include <math.h>

#define B_  2
#define T_  1024
#define C_  2048
#define H_  16
#define D_  128
#define M_  (B_*T_)

// Scratch (allocation-free rule: device globals)
__device__ float g_q[(size_t)M_*C_];
__device__ float g_k[(size_t)M_*C_];
__device__ float g_v[(size_t)M_*C_];
__device__ float g_y[(size_t)M_*C_];

// ===================== SGEMM NT: C[m,n] = sum_k A[m,k]*B[n,k] =====================
// A: [M,K] row-major, Bw: [N,K] row-major (torch Linear weight), C: [M,N]
#define GBM 128
#define GBN 128
#define GBK 16
#define GLD 132   // padded row stride (floats) for the [BK][BM] transposed tiles

__global__ __launch_bounds__(256, 2)
void sgemm_nt(const float* __restrict__ A, const float* __restrict__ Bw,
              float* __restrict__ Cout, int Ndim, int Kdim)
{
    __shared__ float As[GBK][GLD];
    __shared__ float Bs[GBK][GLD];
    const int tid = threadIdx.x;
    const int tx  = tid & 15;
    const int ty  = tid >> 4;
    const int m0  = blockIdx.y * GBM;
    const int n0  = blockIdx.x * GBN;

    float acc[8][8];
    #pragma unroll
    for (int i = 0; i < 8; i++)
        #pragma unroll
        for (int j = 0; j < 8; j++) acc[i][j] = 0.f;

    for (int k0 = 0; k0 < Kdim; k0 += GBK) {
        // Load 128x16 tiles of A and B, transposed into [k][m] layout.
        #pragma unroll
        for (int it = 0; it < 2; it++) {
            int idx = tid + 256*it;
            int r   = idx >> 2;          // 0..127
            int kq  = (idx & 3) << 2;    // 0,4,8,12
            float4 va = *reinterpret_cast<const float4*>(A + (size_t)(m0 + r)*Kdim + k0 + kq);
            As[kq+0][r] = va.x; As[kq+1][r] = va.y; As[kq+2][r] = va.z; As[kq+3][r] = va.w;
            float4 vb = *reinterpret_cast<const float4*>(Bw + (size_t)(n0 + r)*Kdim + k0 + kq);
            Bs[kq+0][r] = vb.x; Bs[kq+1][r] = vb.y; Bs[kq+2][r] = vb.z; Bs[kq+3][r] = vb.w;
        }
        __syncthreads();

        #pragma unroll
        for (int kk = 0; kk < GBK; kk++) {
            float4 a0 = *reinterpret_cast<const float4*>(&As[kk][ty*4]);
            float4 a1 = *reinterpret_cast<const float4*>(&As[kk][ty*4 + 64]);
            float4 b0 = *reinterpret_cast<const float4*>(&Bs[kk][tx*4]);
            float4 b1 = *reinterpret_cast<const float4*>(&Bs[kk][tx*4 + 64]);
            float ar[8] = {a0.x,a0.y,a0.z,a0.w, a1.x,a1.y,a1.z,a1.w};
            float br[8] = {b0.x,b0.y,b0.z,b0.w, b1.x,b1.y,b1.z,b1.w};
            #pragma unroll
            for (int i = 0; i < 8; i++)
                #pragma unroll
                for (int j = 0; j < 8; j++)
                    acc[i][j] += ar[i]*br[j];
        }
        __syncthreads();
    }

    #pragma unroll
    for (int i = 0; i < 8; i++) {
        int row = m0 + ty*4 + (i & 3) + ((i >> 2) << 6);
        float* cp = Cout + (size_t)row*Ndim + n0 + tx*4;
        *reinterpret_cast<float4*>(cp)      = make_float4(acc[i][0], acc[i][1], acc[i][2], acc[i][3]);
        *reinterpret_cast<float4*>(cp + 64) = make_float4(acc[i][4], acc[i][5], acc[i][6], acc[i][7]);
    }
}

// ===================== RoPE (in-place on q and k) =====================
// element (row=b*T+t, h, d): pair (d, d+64), angle = t * 10000^(-d/64)
__global__ void rope_kernel(float* __restrict__ q, float* __restrict__ k)
{
    int idx = blockIdx.x * blockDim.x + threadIdx.x;   // 0 .. M_*C_/2 - 1
    int row = idx >> 10;            // C_/2 = 1024 pairs per row
    int w   = idx & 1023;
    int h   = w >> 6;
    int dp  = w & 63;
    int t   = row & (T_ - 1);

    double invf = pow(10000.0, -(double)dp * (1.0/64.0));
    float ang = (float)((double)t * invf);
    float s, c;
    sincosf(ang, &s, &c);

    size_t base = (size_t)row*C_ + (size_t)h*D_ + dp;
    float a0 = q[base], b0 = q[base + 64];
    q[base]      = a0*c - b0*s;
    q[base + 64] = b0*c + a0*s;
    a0 = k[base]; b0 = k[base + 64];
    k[base]      = a0*c - b0*s;
    k[base + 64] = b0*c + a0*s;
}

// ===================== Flash attention (causal, fp32) =====================
// Layout of q/k/v/y: [b, t, h, d]  (element offset b*T*C + t*C + h*D + d)
#define FBM 64
#define FLD 132    // padded row stride for 64x128 Q/K/V tiles
#define FLDS 65    // padded row stride for 64x64 S tile
#define ATT_SCALE 0.08838834764831845f   // 1/sqrt(128)

__global__ __launch_bounds__(256, 1)
void flash_attn(const float* __restrict__ Q, const float* __restrict__ K,
                const float* __restrict__ V, float* __restrict__ Y)
{
    extern __shared__ float sm[];
    float* Qs  = sm;                     // 64*132
    float* Ks  = Qs + FBM*FLD;           // 64*132
    float* Vs  = Ks + FBM*FLD;           // 64*132
    float* Ss  = Vs + FBM*FLD;           // 64*65
    float* msh = Ss + FBM*FLDS;          // 64
    float* lsh = msh + FBM;              // 64
    float* fsh = lsh + FBM;              // 64

    const int tid  = threadIdx.x;
    const int tx   = tid & 15;
    const int ty   = tid >> 4;
    const int lane = tid & 31;
    const int wid  = tid >> 5;

    // heavy (long-diagonal) q-tiles first for wave balance
    const int qt = (int)gridDim.x - 1 - (int)blockIdx.x;
    const int bh = blockIdx.y;
    const int b  = bh >> 4;
    const int h  = bh & (H_ - 1);
    const int q0 = qt * FBM;

    const float* Qb = Q + (size_t)b*T_*C_ + (size_t)h*D_;
    const float* Kb = K + (size_t)b*T_*C_ + (size_t)h*D_;
    const float* Vb = V + (size_t)b*T_*C_ + (size_t)h*D_;

    // Load Q tile [64 x 128]
    #pragma unroll
    for (int it = 0; it < 8; it++) {
        int r = wid + 8*it;
        *reinterpret_cast<float4*>(&Qs[r*FLD + lane*4]) =
            *reinterpret_cast<const float4*>(Qb + (size_t)(q0 + r)*C_ + lane*4);
    }
    if (tid < FBM) { msh[tid] = -1e30f; lsh[tid] = 0.f; }

    float acco[4][8];
    #pragma unroll
    for (int r = 0; r < 4; r++)
        #pragma unroll
        for (int c = 0; c < 8; c++) acco[r][c] = 0.f;

    const int ntiles = qt + 1;
    for (int kt = 0; kt < ntiles; kt++) {
        const int k0 = kt * FBM;
        __syncthreads();   // prev PV done (Vs/Ss free), Q tile visible on first iter
        #pragma unroll
        for (int it = 0; it < 8; it++) {
            int r = wid + 8*it;
            *reinterpret_cast<float4*>(&Ks[r*FLD + lane*4]) =
                *reinterpret_cast<const float4*>(Kb + (size_t)(k0 + r)*C_ + lane*4);
            *reinterpret_cast<float4*>(&Vs[r*FLD + lane*4]) =
                *reinterpret_cast<const float4*>(Vb + (size_t)(k0 + r)*C_ + lane*4);
        }
        __syncthreads();

        // S = Q K^T  (64x64, rows ty+16r, cols tx+16c — bank-conflict-free LDS.128)
        float accs[4][4];
        #pragma unroll
        for (int r = 0; r < 4; r++)
            #pragma unroll
            for (int c = 0; c < 4; c++) accs[r][c] = 0.f;

        #pragma unroll 4
        for (int d4 = 0; d4 < D_/4; d4++) {
            float4 qa[4], kb[4];
            #pragma unroll
            for (int r = 0; r < 4; r++)
                qa[r] = *reinterpret_cast<const float4*>(&Qs[(ty + 16*r)*FLD + d4*4]);
            #pragma unroll
            for (int c = 0; c < 4; c++)
                kb[c] = *reinterpret_cast<const float4*>(&Ks[(tx + 16*c)*FLD + d4*4]);
            #pragma unroll
            for (int r = 0; r < 4; r++)
                #pragma unroll
                for (int c = 0; c < 4; c++) {
                    accs[r][c] += qa[r].x * kb[c].x;
                    accs[r][c] += qa[r].y * kb[c].y;
                    accs[r][c] += qa[r].z * kb[c].z;
                    accs[r][c] += qa[r].w * kb[c].w;
                }
        }

        // scale + causal mask (only the diagonal tile needs masking) -> Ss
        const bool diag = (kt == ntiles - 1);
        #pragma unroll
        for (int r = 0; r < 4; r++) {
            int lr = ty + 16*r;
            #pragma unroll
            for (int c = 0; c < 4; c++) {
                int lc = tx + 16*c;
                float v = accs[r][c] * ATT_SCALE;
                if (diag && (k0 + lc > q0 + lr)) v = -1e30f;
                Ss[lr*FLDS + lc] = v;
            }
        }
        __syncthreads();

        // online softmax: warp w owns rows [8w, 8w+8)
        #pragma unroll
        for (int rr = 0; rr < 8; rr++) {
            int r = wid*8 + rr;
            float v0 = Ss[r*FLDS + lane];
            float v1 = Ss[r*FLDS + lane + 32];
            float mx = fmaxf(v0, v1);
            #pragma unroll
            for (int o = 16; o > 0; o >>= 1)
                mx = fmaxf(mx, __shfl_xor_sync(0xffffffffu, mx, o));
            float mold = msh[r];
            float mnew = fmaxf(mold, mx);
            float p0 = __expf(v0 - mnew);
            float p1 = __expf(v1 - mnew);
            Ss[r*FLDS + lane]      = p0;
            Ss[r*FLDS + lane + 32] = p1;
            float sum = p0 + p1;
            #pragma unroll
            for (int o = 16; o > 0; o >>= 1)
                sum += __shfl_xor_sync(0xffffffffu, sum, o);
            if (lane == 0) {
                float f = __expf(mold - mnew);
                fsh[r] = f;
                lsh[r] = lsh[r]*f + sum;
                msh[r] = mnew;
            }
        }
        __syncthreads();

        // rescale O, then O += P V  (rows ty+16r, cols tx*4+{0..3} and +64)
        float fr[4];
        #pragma unroll
        for (int r = 0; r < 4; r++) fr[r] = fsh[ty + 16*r];
        #pragma unroll
        for (int r = 0; r < 4; r++)
            #pragma unroll
            for (int c = 0; c < 8; c++) acco[r][c] *= fr[r];

        #pragma unroll 4
        for (int j = 0; j < FBM; j++) {
            float4 va = *reinterpret_cast<const float4*>(&Vs[j*FLD + tx*4]);
            float4 vb = *reinterpret_cast<const float4*>(&Vs[j*FLD + tx*4 + 64]);
            #pragma unroll
            for (int r = 0; r < 4; r++) {
                float p = Ss[(ty + 16*r)*FLDS + j];
                acco[r][0] += p*va.x; acco[r][1] += p*va.y;
                acco[r][2] += p*va.z; acco[r][3] += p*va.w;
                acco[r][4] += p*vb.x; acco[r][5] += p*vb.y;
                acco[r][6] += p*vb.z; acco[r][7] += p*vb.w;
            }
        }
    }

    // normalize + write y[b, t, h, :]
    float* Yb = Y + (size_t)b*T_*C_ + (size_t)h*D_;
    #pragma unroll
    for (int r = 0; r < 4; r++) {
        int lr = ty + 16*r;
        float inv = 1.0f / lsh[lr];
        float* dst = Yb + (size_t)(q0 + lr)*C_ + tx*4;
        *reinterpret_cast<float4*>(dst) =
            make_float4(acco[r][0]*inv, acco[r][1]*inv, acco[r][2]*inv, acco[r][3]*inv);
        *reinterpret_cast<float4*>(dst + 64) =
            make_float4(acco[r][4]*inv, acco[r][5]*inv, acco[r][6]*inv, acco[r][7]*inv);
    }
}

// ===================== launch =====================
extern "C" void kernel_launch(void* const* d_in, const int* in_sizes, int n_in,
                              void* d_out, int out_size)
{
    const float* x  = (const float*)d_in[0];
    const float* Wq = (const float*)d_in[1];
    const float* Wk = (const float*)d_in[2];
    const float* Wv = (const float*)d_in[3];
    const float* Wo = (const float*)d_in[4];
    float* out = (float*)d_out;

    float *qp, *kp, *vp, *yp;
    cudaGetSymbolAddress((void**)&qp, g_q);
    cudaGetSymbolAddress((void**)&kp, g_k);
    cudaGetSymbolAddress((void**)&vp, g_v);
    cudaGetSymbolAddress((void**)&yp, g_y);

    const int fsmem = (3*FBM*FLD + FBM*FLDS + 3*FBM) * (int)sizeof(float);  // 118784
    cudaFuncSetAttribute(flash_attn, cudaFuncAttributeMaxDynamicSharedMemorySize, fsmem);

    dim3 gg(C_/GBN, M_/GBM);   // (16,16)
    sgemm_nt<<<gg, 256>>>(x, Wq, qp, C_, C_);
    sgemm_nt<<<gg, 256>>>(x, Wk, kp, C_, C_);
    sgemm_nt<<<gg, 256>>>(x, Wv, vp, C_, C_);

    rope_kernel<<<(M_*(C_/2))/256, 256>>>(qp, kp);

    dim3 ag(T_/FBM, B_*H_);    // (16,32)
    flash_attn<<<ag, 256, fsmem>>>(qp, kp, vp, yp);

    sgemm_nt<<<gg, 256>>>(yp, Wo, out, C_, C_);
}

// round 13
// speedup vs baseline: 1.0016x; 1.0016x over previous
#include <cuda_runtime.h>
#include <math.h>

#define B_  2
#define T_  1024
#define C_  2048
#define H_  16
#define D_  128
#define M_  (B_*T_)

// Scratch (allocation-free rule: device globals)
__device__ float g_q[(size_t)M_*C_];
__device__ float g_k[(size_t)M_*C_];
__device__ float g_v[(size_t)M_*C_];
__device__ float g_y[(size_t)M_*C_];

// ===================== SGEMM NT: C[m,n] = sum_k A[m,k]*B[n,k] =====================
// A: [M,K] row-major, Bw: [N,K] row-major (torch Linear weight), C: [M,N]
#define GBM 128
#define GBN 128
#define GBK 16
#define GLD 132   // padded row stride (floats) for the [BK][BM] transposed tiles

__global__ __launch_bounds__(256, 2)
void sgemm_nt(const float* __restrict__ A, const float* __restrict__ Bw,
              float* __restrict__ Cout, int Ndim, int Kdim)
{
    __shared__ float As[GBK][GLD];
    __shared__ float Bs[GBK][GLD];
    const int tid = threadIdx.x;
    const int tx  = tid & 15;
    const int ty  = tid >> 4;
    const int m0  = blockIdx.y * GBM;
    const int n0  = blockIdx.x * GBN;

    float acc[8][8];
    #pragma unroll
    for (int i = 0; i < 8; i++)
        #pragma unroll
        for (int j = 0; j < 8; j++) acc[i][j] = 0.f;

    for (int k0 = 0; k0 < Kdim; k0 += GBK) {
        // Load 128x16 tiles of A and B, transposed into [k][m] layout.
        #pragma unroll
        for (int it = 0; it < 2; it++) {
            int idx = tid + 256*it;
            int r   = idx >> 2;          // 0..127
            int kq  = (idx & 3) << 2;    // 0,4,8,12
            float4 va = *reinterpret_cast<const float4*>(A + (size_t)(m0 + r)*Kdim + k0 + kq);
            As[kq+0][r] = va.x; As[kq+1][r] = va.y; As[kq+2][r] = va.z; As[kq+3][r] = va.w;
            float4 vb = *reinterpret_cast<const float4*>(Bw + (size_t)(n0 + r)*Kdim + k0 + kq);
            Bs[kq+0][r] = vb.x; Bs[kq+1][r] = vb.y; Bs[kq+2][r] = vb.z; Bs[kq+3][r] = vb.w;
        }
        __syncthreads();

        #pragma unroll
        for (int kk = 0; kk < GBK; kk++) {
            float4 a0 = *reinterpret_cast<const float4*>(&As[kk][ty*4]);
            float4 a1 = *reinterpret_cast<const float4*>(&As[kk][ty*4 + 64]);
            float4 b0 = *reinterpret_cast<const float4*>(&Bs[kk][tx*4]);
            float4 b1 = *reinterpret_cast<const float4*>(&Bs[kk][tx*4 + 64]);
            float ar[8] = {a0.x,a0.y,a0.z,a0.w, a1.x,a1.y,a1.z,a1.w};
            float br[8] = {b0.x,b0.y,b0.z,b0.w, b1.x,b1.y,b1.z,b1.w};
            #pragma unroll
            for (int i = 0; i < 8; i++)
                #pragma unroll
                for (int j = 0; j < 8; j++)
                    acc[i][j] += ar[i]*br[j];
        }
        __syncthreads();
    }

    #pragma unroll
    for (int i = 0; i < 8; i++) {
        int row = m0 + ty*4 + (i & 3) + ((i >> 2) << 6);
        float* cp = Cout + (size_t)row*Ndim + n0 + tx*4;
        *reinterpret_cast<float4*>(cp)      = make_float4(acc[i][0], acc[i][1], acc[i][2], acc[i][3]);
        *reinterpret_cast<float4*>(cp + 64) = make_float4(acc[i][4], acc[i][5], acc[i][6], acc[i][7]);
    }
}

// ===================== RoPE (in-place on q and k) =====================
// element (row=b*T+t, h, d): pair (d, d+64), angle = t * 10000^(-d/64)
__global__ void rope_kernel(float* __restrict__ q, float* __restrict__ k)
{
    int idx = blockIdx.x * blockDim.x + threadIdx.x;   // 0 .. M_*C_/2 - 1
    int row = idx >> 10;            // C_/2 = 1024 pairs per row
    int w   = idx & 1023;
    int h   = w >> 6;
    int dp  = w & 63;
    int t   = row & (T_ - 1);

    double invf = pow(10000.0, -(double)dp * (1.0/64.0));
    float ang = (float)((double)t * invf);
    float s, c;
    sincosf(ang, &s, &c);

    size_t base = (size_t)row*C_ + (size_t)h*D_ + dp;
    float a0 = q[base], b0 = q[base + 64];
    q[base]      = a0*c - b0*s;
    q[base + 64] = b0*c + a0*s;
    a0 = k[base]; b0 = k[base + 64];
    k[base]      = a0*c - b0*s;
    k[base + 64] = b0*c + a0*s;
}

// ===================== Flash attention (causal, fp32) =====================
// Layout of q/k/v/y: [b, t, h, d]  (element offset b*T*C + t*C + h*D + d)
#define FBM 64
#define FLD 132    // padded row stride for 64x128 Q/K/V tiles
#define FLDS 65    // padded row stride for 64x64 S tile
#define ATT_SCALE 0.08838834764831845f   // 1/sqrt(128)

__global__ __launch_bounds__(256, 1)
void flash_attn(const float* __restrict__ Q, const float* __restrict__ K,
                const float* __restrict__ V, float* __restrict__ Y)
{
    extern __shared__ float sm[];
    float* Qs  = sm;                     // 64*132
    float* Ks  = Qs + FBM*FLD;           // 64*132
    float* Vs  = Ks + FBM*FLD;           // 64*132
    float* Ss  = Vs + FBM*FLD;           // 64*65
    float* msh = Ss + FBM*FLDS;          // 64
    float* lsh = msh + FBM;              // 64
    float* fsh = lsh + FBM;              // 64

    const int tid  = threadIdx.x;
    const int tx   = tid & 15;
    const int ty   = tid >> 4;
    const int lane = tid & 31;
    const int wid  = tid >> 5;

    // heavy (long-diagonal) q-tiles first for wave balance
    const int qt = (int)gridDim.x - 1 - (int)blockIdx.x;
    const int bh = blockIdx.y;
    const int b  = bh >> 4;
    const int h  = bh & (H_ - 1);
    const int q0 = qt * FBM;

    const float* Qb = Q + (size_t)b*T_*C_ + (size_t)h*D_;
    const float* Kb = K + (size_t)b*T_*C_ + (size_t)h*D_;
    const float* Vb = V + (size_t)b*T_*C_ + (size_t)h*D_;

    // Load Q tile [64 x 128]
    #pragma unroll
    for (int it = 0; it < 8; it++) {
        int r = wid + 8*it;
        *reinterpret_cast<float4*>(&Qs[r*FLD + lane*4]) =
            *reinterpret_cast<const float4*>(Qb + (size_t)(q0 + r)*C_ + lane*4);
    }
    if (tid < FBM) { msh[tid] = -1e30f; lsh[tid] = 0.f; }

    float acco[4][8];
    #pragma unroll
    for (int r = 0; r < 4; r++)
        #pragma unroll
        for (int c = 0; c < 8; c++) acco[r][c] = 0.f;

    const int ntiles = qt + 1;
    for (int kt = 0; kt < ntiles; kt++) {
        const int k0 = kt * FBM;
        __syncthreads();   // prev PV done (Vs/Ss free), Q tile visible on first iter
        #pragma unroll
        for (int it = 0; it < 8; it++) {
            int r = wid + 8*it;
            *reinterpret_cast<float4*>(&Ks[r*FLD + lane*4]) =
                *reinterpret_cast<const float4*>(Kb + (size_t)(k0 + r)*C_ + lane*4);
            *reinterpret_cast<float4*>(&Vs[r*FLD + lane*4]) =
                *reinterpret_cast<const float4*>(Vb + (size_t)(k0 + r)*C_ + lane*4);
        }
        __syncthreads();

        // S = Q K^T  (64x64, rows ty+16r, cols tx+16c — bank-conflict-free LDS.128)
        float accs[4][4];
        #pragma unroll
        for (int r = 0; r < 4; r++)
            #pragma unroll
            for (int c = 0; c < 4; c++) accs[r][c] = 0.f;

        #pragma unroll 4
        for (int d4 = 0; d4 < D_/4; d4++) {
            float4 qa[4], kb[4];
            #pragma unroll
            for (int r = 0; r < 4; r++)
                qa[r] = *reinterpret_cast<const float4*>(&Qs[(ty + 16*r)*FLD + d4*4]);
            #pragma unroll
            for (int c = 0; c < 4; c++)
                kb[c] = *reinterpret_cast<const float4*>(&Ks[(tx + 16*c)*FLD + d4*4]);
            #pragma unroll
            for (int r = 0; r < 4; r++)
                #pragma unroll
                for (int c = 0; c < 4; c++) {
                    accs[r][c] += qa[r].x * kb[c].x;
                    accs[r][c] += qa[r].y * kb[c].y;
                    accs[r][c] += qa[r].z * kb[c].z;
                    accs[r][c] += qa[r].w * kb[c].w;
                }
        }

        // scale + causal mask (only the diagonal tile needs masking) -> Ss
        const bool diag = (kt == ntiles - 1);
        #pragma unroll
        for (int r = 0; r < 4; r++) {
            int lr = ty + 16*r;
            #pragma unroll
            for (int c = 0; c < 4; c++) {
                int lc = tx + 16*c;
                float v = accs[r][c] * ATT_SCALE;
                if (diag && (k0 + lc > q0 + lr)) v = -1e30f;
                Ss[lr*FLDS + lc] = v;
            }
        }
        __syncthreads();

        // online softmax: warp w owns rows [8w, 8w+8)
        #pragma unroll
        for (int rr = 0; rr < 8; rr++) {
            int r = wid*8 + rr;
            float v0 = Ss[r*FLDS + lane];
            float v1 = Ss[r*FLDS + lane + 32];
            float mx = fmaxf(v0, v1);
            #pragma unroll
            for (int o = 16; o > 0; o >>= 1)
                mx = fmaxf(mx, __shfl_xor_sync(0xffffffffu, mx, o));
            float mold = msh[r];
            float mnew = fmaxf(mold, mx);
            float p0 = __expf(v0 - mnew);
            float p1 = __expf(v1 - mnew);
            Ss[r*FLDS + lane]      = p0;
            Ss[r*FLDS + lane + 32] = p1;
            float sum = p0 + p1;
            #pragma unroll
            for (int o = 16; o > 0; o >>= 1)
                sum += __shfl_xor_sync(0xffffffffu, sum, o);
            if (lane == 0) {
                float f = __expf(mold - mnew);
                fsh[r] = f;
                lsh[r] = lsh[r]*f + sum;
                msh[r] = mnew;
            }
        }
        __syncthreads();

        // rescale O, then O += P V  (rows ty+16r, cols tx*4+{0..3} and +64)
        float fr[4];
        #pragma unroll
        for (int r = 0; r < 4; r++) fr[r] = fsh[ty + 16*r];
        #pragma unroll
        for (int r = 0; r < 4; r++)
            #pragma unroll
            for (int c = 0; c < 8; c++) acco[r][c] *= fr[r];

        #pragma unroll 4
        for (int j = 0; j < FBM; j++) {
            float4 va = *reinterpret_cast<const float4*>(&Vs[j*FLD + tx*4]);
            float4 vb = *reinterpret_cast<const float4*>(&Vs[j*FLD + tx*4 + 64]);
            #pragma unroll
            for (int r = 0; r < 4; r++) {
                float p = Ss[(ty + 16*r)*FLDS + j];
                acco[r][0] += p*va.x; acco[r][1] += p*va.y;
                acco[r][2] += p*va.z; acco[r][3] += p*va.w;
                acco[r][4] += p*vb.x; acco[r][5] += p*vb.y;
                acco[r][6] += p*vb.z; acco[r][7] += p*vb.w;
            }
        }
    }

    // normalize + write y[b, t, h, :]
    float* Yb = Y + (size_t)b*T_*C_ + (size_t)h*D_;
    #pragma unroll
    for (int r = 0; r < 4; r++) {
        int lr = ty + 16*r;
        float inv = 1.0f / lsh[lr];
        float* dst = Yb + (size_t)(q0 + lr)*C_ + tx*4;
        *reinterpret_cast<float4*>(dst) =
            make_float4(acco[r][0]*inv, acco[r][1]*inv, acco[r][2]*inv, acco[r][3]*inv);
        *reinterpret_cast<float4*>(dst + 64) =
            make_float4(acco[r][4]*inv, acco[r][5]*inv, acco[r][6]*inv, acco[r][7]*inv);
    }
}

// ===================== launch =====================
extern "C" void kernel_launch(void* const* d_in, const int* in_sizes, int n_in,
                              void* d_out, int out_size)
{
    const float* x  = (const float*)d_in[0];
    const float* Wq = (const float*)d_in[1];
    const float* Wk = (const float*)d_in[2];
    const float* Wv = (const float*)d_in[3];
    const float* Wo = (const float*)d_in[4];
    float* out = (float*)d_out;

    float *qp, *kp, *vp, *yp;
    cudaGetSymbolAddress((void**)&qp, g_q);
    cudaGetSymbolAddress((void**)&kp, g_k);
    cudaGetSymbolAddress((void**)&vp, g_v);
    cudaGetSymbolAddress((void**)&yp, g_y);

    const int fsmem = (3*FBM*FLD + FBM*FLDS + 3*FBM) * (int)sizeof(float);  // 118784
    cudaFuncSetAttribute(flash_attn, cudaFuncAttributeMaxDynamicSharedMemorySize, fsmem);

    dim3 gg(C_/GBN, M_/GBM);   // (16,16)
    sgemm_nt<<<gg, 256>>>(x, Wq, qp, C_, C_);
    sgemm_nt<<<gg, 256>>>(x, Wk, kp, C_, C_);
    sgemm_nt<<<gg, 256>>>(x, Wv, vp, C_, C_);

    rope_kernel<<<(M_*(C_/2))/256, 256>>>(qp, kp);

    dim3 ag(T_/FBM, B_*H_);    // (16,32)
    flash_attn<<<ag, 256, fsmem>>>(qp, kp, vp, yp);

    sgemm_nt<<<gg, 256>>>(yp, Wo, out, C_, C_);
}